// round 13
// baseline (speedup 1.0000x reference)
#include <cuda_runtime.h>
#include <cuda_fp16.h>
#include <cstdint>

// ===================== problem constants =====================
// x: 262144 rows x 128; W: (8,128,128); b: (8,128)
// CTA job: 128 rows (M) x 128 cols (N) x K=128. Channel constant per 2 jobs.
// Single kernel: each CTA builds its channel's W fp16 fragment image in smem
// directly from raw fp32 W (no prep kernel, no second launch).
#define N_DIM      128
#define K_DIM      128
#define THREADS    256
#define NUM_CTAS   2048
#define K_CHUNK    32
#define NCHUNK     4

// ---- smem layout (32-bit words) ----
// [W fp16 frag image: 8192 words][A fp16 2 bufs: 2x2560 words][bias 128]
#define OFF_W       0
#define W_IMG_WORDS 8192
#define F16_STRIDE_H 40                       // halves per A row -> LDSM conflict-free
#define F16_BUF_WORDS (128 * 20)              // 2560 words = 10KB per parity buf
#define OFF_A       W_IMG_WORDS               // 8192
#define OFF_BIAS    (OFF_A + 2 * F16_BUF_WORDS)   // 13312
#define SMEM_FLOATS (OFF_BIAS + 128)
#define SMEM_BYTES  (SMEM_FLOATS * 4)         // 53,760 (x2 CTAs = 107.5KB)

// ===================== helpers =====================
__device__ __forceinline__ uint32_t smem_u32(const void* p) {
    uint32_t a;
    asm("{ .reg .u64 t; cvta.to.shared.u64 t, %1; cvt.u32.u64 %0, t; }" : "=r"(a) : "l"(p));
    return a;
}
__device__ __forceinline__ void ldsm_x4(uint32_t& r0, uint32_t& r1, uint32_t& r2, uint32_t& r3,
                                        uint32_t addr) {
    asm volatile("ldmatrix.sync.aligned.m8n8.x4.shared.b16 {%0,%1,%2,%3}, [%4];"
                 : "=r"(r0), "=r"(r1), "=r"(r2), "=r"(r3) : "r"(addr));
}
// m16n8k16 fp16 MMA, fp32 accumulate
__device__ __forceinline__ void mma_f16(float* c, const uint32_t* a, uint32_t b0, uint32_t b1) {
    asm volatile(
        "mma.sync.aligned.m16n8k16.row.col.f32.f16.f16.f32 "
        "{%0,%1,%2,%3}, {%4,%5,%6,%7}, {%8,%9}, {%0,%1,%2,%3};"
        : "+f"(c[0]), "+f"(c[1]), "+f"(c[2]), "+f"(c[3])
        : "r"(a[0]), "r"(a[1]), "r"(a[2]), "r"(a[3]), "r"(b0), "r"(b1));
}

// ===================== main GEMM (single kernel) =====================
__global__ __launch_bounds__(THREADS, 2)
void gemm_kernel(const float* __restrict__ x, const float* __restrict__ Wraw,
                 const float* __restrict__ bias, float* __restrict__ out) {
    extern __shared__ __align__(16) float smem[];
    const uint32_t sm_base = smem_u32(smem);

    const int tid  = threadIdx.x;
    const int lane = tid & 31;
    const int wid  = tid >> 5;
    const int blk  = blockIdx.x;
    const int ch   = (blk >> 1) & 7;

    const float* a_base = x + (size_t)blk * (128 * K_DIM);
    float*       o_base = out + (size_t)blk * (128 * N_DIM);

    // per-thread A piece coordinates: pid = i*256+tid -> row pid>>3, 4-col group pid&7
    const int arow = tid >> 3;          // rows handled: arow, arow+32, arow+64, arow+96
    const int apc  = tid & 7;

    // ---- prologue part 1: issue chunk-0 A LDGs first (longest latency) ----
    float4 v[4];
#pragma unroll
    for (int i = 0; i < 4; i++)
        v[i] = *(const float4*)(a_base + (size_t)(arow + i * 32) * K_DIM + apc * 4);

    // ---- prologue part 2: build W fp16 fragment image in smem from raw W ----
    // Image (validated rounds 8-12): per kc, 512 float4s; fi4 = (p*2+ks)*32 + l holds
    // { b0(nt=2p), b1(nt=2p), b0(nt=2p+1), b1(nt=2p+1) } with
    // n_e = 16p + (l>>2), k0 = kc*32 + ks*16 + (l&3)*2; bX pairs = {k0,k0+1}/{k0+8,k0+9}.
    {
        const float* Wch = Wraw + ch * (N_DIM * K_DIM);
        uint32_t* const wimg = (uint32_t*)smem + OFF_W;
#pragma unroll
        for (int j = 0; j < 8; j++) {
            int fid = j * THREADS + tid;        // 0..2047 image float4s
            int kc = fid >> 9;
            int rem = fid & 511;
            int p  = rem >> 6;
            int ks = (rem >> 5) & 1;
            int l  = rem & 31;
            int ne = (p << 4) + (l >> 2);
            int k0 = kc * 32 + ks * 16 + (l & 3) * 2;
            const float* w0 = Wch + ne * K_DIM + k0;
            float2 we0 = *(const float2*)(w0);
            float2 we1 = *(const float2*)(w0 + 8);
            float2 wo0 = *(const float2*)(w0 + 8 * K_DIM);
            float2 wo1 = *(const float2*)(w0 + 8 * K_DIM + 8);
            __half2 he0 = __float22half2_rn(we0);
            __half2 he1 = __float22half2_rn(we1);
            __half2 ho0 = __float22half2_rn(wo0);
            __half2 ho1 = __float22half2_rn(wo1);
            uint4 pk;
            pk.x = *(uint32_t*)&he0;
            pk.y = *(uint32_t*)&he1;
            pk.z = *(uint32_t*)&ho0;
            pk.w = *(uint32_t*)&ho1;
            *(uint4*)(wimg + fid * 4) = pk;
        }
    }
    if (tid < 128) smem[OFF_BIAS + tid] = bias[ch * 128 + tid];

    // ---- prologue part 3: STS chunk 0 -> buf 0, then single barrier ----
    uint32_t* const abufw = (uint32_t*)(smem + OFF_A);
#pragma unroll
    for (int i = 0; i < 4; i++) {
        __half2 h0 = __float22half2_rn(make_float2(v[i].x, v[i].y));
        __half2 h1 = __float22half2_rn(make_float2(v[i].z, v[i].w));
        uint2 pk; pk.x = *(uint32_t*)&h0; pk.y = *(uint32_t*)&h1;
        *(uint2*)(abufw + (arow + i * 32) * 20 + apc * 2) = pk;
    }
    __syncthreads();                     // W image + bias + A buf0 visible

    // 8 warps: 4 over M (32 rows each), 2 over N (64 cols each)
    const int warpM = (wid >> 1) * 32;
    const int h     = (wid & 1);

    float acc[2][8][4];
#pragma unroll
    for (int mt = 0; mt < 2; mt++)
#pragma unroll
        for (int nt = 0; nt < 8; nt++)
#pragma unroll
            for (int q = 0; q < 4; q++) acc[mt][nt][q] = 0.0f;

    // LDSM per-lane base (halves): row = warpM + (lane&7) + ((lane>>3)&1)*8, +8 halves lanes 16-31
    const uint32_t a_lane_h =
        (uint32_t)((warpM + (lane & 7) + ((lane >> 3) & 1) * 8) * F16_STRIDE_H
                   + (lane >> 4) * 8);
    const uint32_t f16_base = sm_base + OFF_A * 4u;

#pragma unroll
    for (int kc = 0; kc < NCHUNK; kc++) {
        const int par = kc & 1;

        // LDG next chunk (covered by the MMA block below)
        if (kc < NCHUNK - 1) {
#pragma unroll
            for (int i = 0; i < 4; i++)
                v[i] = *(const float4*)(a_base + (size_t)(arow + i * 32) * K_DIM
                                        + (kc + 1) * K_CHUNK + apc * 4);
        }

        // ---- MMA phase on buf[par], W frags for this kc ----
        const float4* bW = (const float4*)(smem + OFF_W) + kc * 512 + h * 256 + lane;
        const uint32_t aL = f16_base + (uint32_t)(par * F16_BUF_WORDS) * 4u + a_lane_h * 2u;

        uint32_t afr[2][2][4];
#pragma unroll
        for (int mt = 0; mt < 2; mt++)
            ldsm_x4(afr[0][mt][0], afr[0][mt][1], afr[0][mt][2], afr[0][mt][3],
                    aL + (uint32_t)(mt * 16 * F16_STRIDE_H * 2));

#pragma unroll
        for (int ks = 0; ks < 2; ks++) {
            float4 f0 = bW[0 * 64 + ks * 32];
            float4 f1 = bW[1 * 64 + ks * 32];
            float4 f2 = bW[2 * 64 + ks * 32];
            float4 f3 = bW[3 * 64 + ks * 32];

            if (ks == 0) {
#pragma unroll
                for (int mt = 0; mt < 2; mt++)
                    ldsm_x4(afr[1][mt][0], afr[1][mt][1], afr[1][mt][2], afr[1][mt][3],
                            aL + (uint32_t)((mt * 16 * F16_STRIDE_H + 16) * 2));
            }

            const float4 fr[4] = {f0, f1, f2, f3};
#pragma unroll
            for (int p = 0; p < 4; p++) {
                uint32_t b0e = __float_as_uint(fr[p].x), b1e = __float_as_uint(fr[p].y);
                uint32_t b0o = __float_as_uint(fr[p].z), b1o = __float_as_uint(fr[p].w);
                mma_f16(acc[0][2 * p],     afr[ks][0], b0e, b1e);
                mma_f16(acc[0][2 * p + 1], afr[ks][0], b0o, b1o);
                mma_f16(acc[1][2 * p],     afr[ks][1], b0e, b1e);
                mma_f16(acc[1][2 * p + 1], afr[ks][1], b0o, b1o);
            }
        }

        // ---- cvt + STS next chunk into opposite buffer; single barrier ----
        if (kc < NCHUNK - 1) {
            const int npar = par ^ 1;
#pragma unroll
            for (int i = 0; i < 4; i++) {
                __half2 h0 = __float22half2_rn(make_float2(v[i].x, v[i].y));
                __half2 h1 = __float22half2_rn(make_float2(v[i].z, v[i].w));
                uint2 pk; pk.x = *(uint32_t*)&h0; pk.y = *(uint32_t*)&h1;
                *(uint2*)(abufw + npar * F16_BUF_WORDS + (arow + i * 32) * 20 + apc * 2) = pk;
            }
            __syncthreads();
        }
    }

    // ---- epilogue: accum + bias -> gmem (float2, full 32B sectors) ----
    const float* sB = smem + OFF_BIAS;
    const int r0 = warpM + (lane >> 2);
    const int n0 = h * 64 + (lane & 3) * 2;
#pragma unroll
    for (int mt = 0; mt < 2; mt++) {
#pragma unroll
        for (int hh = 0; hh < 2; hh++) {
            int row = r0 + mt * 16 + hh * 8;
            float* orow = o_base + (size_t)row * N_DIM;
#pragma unroll
            for (int nt = 0; nt < 8; nt++) {
                int n = n0 + nt * 8;
                float2 vv;
                vv.x = acc[mt][nt][hh * 2 + 0] + sB[n];
                vv.y = acc[mt][nt][hh * 2 + 1] + sB[n + 1];
                *(float2*)(orow + n) = vv;
            }
        }
    }
}

// ===================== launch (single kernel) =====================
extern "C" void kernel_launch(void* const* d_in, const int* in_sizes, int n_in,
                              void* d_out, int out_size) {
    const float* x = (const float*)d_in[0];
    const float* W = (const float*)d_in[1];
    const float* b = (const float*)d_in[2];
    float* out = (float*)d_out;

    cudaFuncSetAttribute(gemm_kernel, cudaFuncAttributeMaxDynamicSharedMemorySize, SMEM_BYTES);
    gemm_kernel<<<NUM_CTAS, THREADS, SMEM_BYTES>>>(x, W, b, out);
}

// round 14
// speedup vs baseline: 1.0409x; 1.0409x over previous
#include <cuda_runtime.h>
#include <cuda_fp16.h>
#include <cstdint>

// ===================== problem constants =====================
// x: 262144 rows x 128; W: (8,128,128); b: (8,128)
// CTA job: 128 rows (M) x 128 cols (N) x K=128. Channel constant per 2 jobs.
#define N_DIM      128
#define K_DIM      128
#define THREADS    256
#define NUM_CTAS   2048
#define K_CHUNK    32
#define NCHUNK     4

// ---- smem layout (32-bit words) ----
// [W fp16 frag image: 8192 words][A fp16 2 bufs: 2x2560 words][bias 128]
#define OFF_W       0
#define W_IMG_WORDS 8192
#define F16_STRIDE_H 40                       // halves per A row -> LDSM conflict-free
#define F16_BUF_WORDS (128 * 20)              // 2560 words = 10KB per parity buf
#define OFF_A       W_IMG_WORDS               // 8192
#define OFF_BIAS    (OFF_A + 2 * F16_BUF_WORDS)   // 13312
#define SMEM_FLOATS (OFF_BIAS + 128)
#define SMEM_BYTES  (SMEM_FLOATS * 4)         // 53,760 (x2 CTAs = 107.5KB)

// ===================== helpers =====================
__device__ __forceinline__ uint32_t smem_u32(const void* p) {
    uint32_t a;
    asm("{ .reg .u64 t; cvta.to.shared.u64 t, %1; cvt.u32.u64 %0, t; }" : "=r"(a) : "l"(p));
    return a;
}
__device__ __forceinline__ void cp_async16(uint32_t dst, const void* src) {
    asm volatile("cp.async.cg.shared.global [%0], [%1], 16;" :: "r"(dst), "l"(src));
}
#define CP_COMMIT()  asm volatile("cp.async.commit_group;" ::: "memory")
#define CP_WAIT(n)   asm volatile("cp.async.wait_group %0;" :: "n"(n) : "memory")

// streaming (evict-first) 128-bit load / 64-bit store
__device__ __forceinline__ float4 ldcs4(const float* p) {
    float4 v;
    asm volatile("ld.global.cs.v4.f32 {%0,%1,%2,%3}, [%4];"
                 : "=f"(v.x), "=f"(v.y), "=f"(v.z), "=f"(v.w) : "l"(p));
    return v;
}
__device__ __forceinline__ void stcs2(float* p, float a, float b) {
    asm volatile("st.global.cs.v2.f32 [%0], {%1,%2};" :: "l"(p), "f"(a), "f"(b));
}

__device__ __forceinline__ void ldsm_x4(uint32_t& r0, uint32_t& r1, uint32_t& r2, uint32_t& r3,
                                        uint32_t addr) {
    asm volatile("ldmatrix.sync.aligned.m8n8.x4.shared.b16 {%0,%1,%2,%3}, [%4];"
                 : "=r"(r0), "=r"(r1), "=r"(r2), "=r"(r3) : "r"(addr));
}
// m16n8k16 fp16 MMA, fp32 accumulate
__device__ __forceinline__ void mma_f16(float* c, const uint32_t* a, uint32_t b0, uint32_t b1) {
    asm volatile(
        "mma.sync.aligned.m16n8k16.row.col.f32.f16.f16.f32 "
        "{%0,%1,%2,%3}, {%4,%5,%6,%7}, {%8,%9}, {%0,%1,%2,%3};"
        : "+f"(c[0]), "+f"(c[1]), "+f"(c[2]), "+f"(c[3])
        : "r"(a[0]), "r"(a[1]), "r"(a[2]), "r"(a[3]), "r"(b0), "r"(b1));
}

// ===================== W fp16 fragment image (validated rounds 8-13) =====================
// Per (ch, kc): 4096 halves (512 float4s). fi4 = (p*2+ks)*32+lane holds
// { b0(nt=2p), b1(nt=2p), b0(nt=2p+1), b1(nt=2p+1) } fp16x2 fragments.
__device__ __align__(16) __half g_Wimg[8 * 4 * 4096];

__global__ void prep_w_kernel(const float* __restrict__ W) {
    int idx = blockIdx.x * blockDim.x + threadIdx.x;   // 0 .. 131071
    if (idx >= 8 * 128 * 128) return;
    int ch = idx >> 14;
    int n  = (idx >> 7) & 127;
    int k  = idx & 127;
    int kc = k >> 5;
    int ks = (k >> 4) & 1;
    int bix = (k >> 3) & 1;
    int hsel = k & 1;
    int lane = ((n & 7) << 2) | ((k >> 1) & 3);
    int p = n >> 4;
    int ntodd = (n >> 3) & 1;
    int e = ntodd * 2 + bix;
    int fi4 = (p * 2 + ks) * 32 + lane;
    g_Wimg[(ch * 4 + kc) * 4096 + fi4 * 8 + e * 2 + hsel] = __float2half_rn(W[idx]);
}

// ===================== main GEMM =====================
__global__ __launch_bounds__(THREADS, 2)
void gemm_kernel(const float* __restrict__ x, const float* __restrict__ bias,
                 float* __restrict__ out) {
    extern __shared__ __align__(16) float smem[];
    const uint32_t sm_base = smem_u32(smem);

    const int tid  = threadIdx.x;
    const int lane = tid & 31;
    const int wid  = tid >> 5;
    const int blk  = blockIdx.x;
    const int ch   = (blk >> 1) & 7;

    const float* a_base = x + (size_t)blk * (128 * K_DIM);
    float*       o_base = out + (size_t)blk * (128 * N_DIM);

    // ---- prologue: W image (32KB, L2-resident) via cp.async; bias; A chunk 0 ----
    {
        const __half* wsrc = g_Wimg + ch * 16384;
        uint32_t sw = sm_base + OFF_W * 4u;
#pragma unroll
        for (int j = 0; j < 8; j++) {
            int pid = j * THREADS + tid;
            cp_async16(sw + (uint32_t)pid * 16u, wsrc + pid * 8);
        }
        CP_COMMIT();
    }
    if (tid < 128) smem[OFF_BIAS + tid] = bias[ch * 128 + tid];

    // 8 warps: 4 over M (32 rows each), 2 over N (64 cols each)
    const int warpM = (wid >> 1) * 32;
    const int h     = (wid & 1);

    float acc[2][8][4];
#pragma unroll
    for (int mt = 0; mt < 2; mt++)
#pragma unroll
        for (int nt = 0; nt < 8; nt++)
#pragma unroll
            for (int q = 0; q < 4; q++) acc[mt][nt][q] = 0.0f;

    uint32_t* const abufw = (uint32_t*)(smem + OFF_A);   // word view of fp16 bufs

    // per-thread A piece coordinates: pid = i*256+tid -> row pid>>3, 4-col group pid&7
    const int arow = tid >> 3;          // rows handled: arow, arow+32, arow+64, arow+96
    const int apc  = tid & 7;

    // LDG chunk 0 (streaming, evict-first: A is read exactly once)
    float4 v[4];
#pragma unroll
    for (int i = 0; i < 4; i++)
        v[i] = ldcs4(a_base + (size_t)(arow + i * 32) * K_DIM + apc * 4);

    // STS chunk 0 -> buf 0 (before the single prologue barrier)
#pragma unroll
    for (int i = 0; i < 4; i++) {
        __half2 h0 = __float22half2_rn(make_float2(v[i].x, v[i].y));
        __half2 h1 = __float22half2_rn(make_float2(v[i].z, v[i].w));
        uint2 pk; pk.x = *(uint32_t*)&h0; pk.y = *(uint32_t*)&h1;
        *(uint2*)(abufw + (arow + i * 32) * 20 + apc * 2) = pk;
    }

    CP_WAIT(0);
    __syncthreads();                     // W image + bias + A buf0 visible (merged barrier)

    // LDSM per-lane base (halves): row = warpM + (lane&7) + ((lane>>3)&1)*8, +8 halves lanes 16-31
    const uint32_t a_lane_h =
        (uint32_t)((warpM + (lane & 7) + ((lane >> 3) & 1) * 8) * F16_STRIDE_H
                   + (lane >> 4) * 8);
    const uint32_t f16_base = sm_base + OFF_A * 4u;

#pragma unroll
    for (int kc = 0; kc < NCHUNK; kc++) {
        const int par = kc & 1;

        // LDG next chunk (streaming; covered by the MMA block below)
        if (kc < NCHUNK - 1) {
#pragma unroll
            for (int i = 0; i < 4; i++)
                v[i] = ldcs4(a_base + (size_t)(arow + i * 32) * K_DIM
                             + (kc + 1) * K_CHUNK + apc * 4);
        }

        // ---- MMA phase on buf[par], W frags for this kc ----
        const float4* bW = (const float4*)(smem + OFF_W) + kc * 512 + h * 256 + lane;
        const uint32_t aL = f16_base + (uint32_t)(par * F16_BUF_WORDS) * 4u + a_lane_h * 2u;

        uint32_t afr[2][2][4];
#pragma unroll
        for (int mt = 0; mt < 2; mt++)
            ldsm_x4(afr[0][mt][0], afr[0][mt][1], afr[0][mt][2], afr[0][mt][3],
                    aL + (uint32_t)(mt * 16 * F16_STRIDE_H * 2));

#pragma unroll
        for (int ks = 0; ks < 2; ks++) {
            float4 f0 = bW[0 * 64 + ks * 32];
            float4 f1 = bW[1 * 64 + ks * 32];
            float4 f2 = bW[2 * 64 + ks * 32];
            float4 f3 = bW[3 * 64 + ks * 32];

            if (ks == 0) {
#pragma unroll
                for (int mt = 0; mt < 2; mt++)
                    ldsm_x4(afr[1][mt][0], afr[1][mt][1], afr[1][mt][2], afr[1][mt][3],
                            aL + (uint32_t)((mt * 16 * F16_STRIDE_H + 16) * 2));
            }

            const float4 fr[4] = {f0, f1, f2, f3};
#pragma unroll
            for (int p = 0; p < 4; p++) {
                uint32_t b0e = __float_as_uint(fr[p].x), b1e = __float_as_uint(fr[p].y);
                uint32_t b0o = __float_as_uint(fr[p].z), b1o = __float_as_uint(fr[p].w);
                mma_f16(acc[0][2 * p],     afr[ks][0], b0e, b1e);
                mma_f16(acc[0][2 * p + 1], afr[ks][0], b0o, b1o);
                mma_f16(acc[1][2 * p],     afr[ks][1], b0e, b1e);
                mma_f16(acc[1][2 * p + 1], afr[ks][1], b0o, b1o);
            }
        }

        // ---- cvt + STS next chunk into opposite buffer; single barrier ----
        if (kc < NCHUNK - 1) {
            const int npar = par ^ 1;
#pragma unroll
            for (int i = 0; i < 4; i++) {
                __half2 h0 = __float22half2_rn(make_float2(v[i].x, v[i].y));
                __half2 h1 = __float22half2_rn(make_float2(v[i].z, v[i].w));
                uint2 pk; pk.x = *(uint32_t*)&h0; pk.y = *(uint32_t*)&h1;
                *(uint2*)(abufw + npar * F16_BUF_WORDS + (arow + i * 32) * 20 + apc * 2) = pk;
            }
            __syncthreads();
        }
    }

    // ---- epilogue: accum + bias -> gmem (streaming float2 stores) ----
    const float* sB = smem + OFF_BIAS;
    const int r0 = warpM + (lane >> 2);
    const int n0 = h * 64 + (lane & 3) * 2;
#pragma unroll
    for (int mt = 0; mt < 2; mt++) {
#pragma unroll
        for (int hh = 0; hh < 2; hh++) {
            int row = r0 + mt * 16 + hh * 8;
            float* orow = o_base + (size_t)row * N_DIM;
#pragma unroll
            for (int nt = 0; nt < 8; nt++) {
                int n = n0 + nt * 8;
                stcs2(orow + n,
                      acc[mt][nt][hh * 2 + 0] + sB[n],
                      acc[mt][nt][hh * 2 + 1] + sB[n + 1]);
            }
        }
    }
}

// ===================== launch =====================
extern "C" void kernel_launch(void* const* d_in, const int* in_sizes, int n_in,
                              void* d_out, int out_size) {
    const float* x = (const float*)d_in[0];
    const float* W = (const float*)d_in[1];
    const float* b = (const float*)d_in[2];
    float* out = (float*)d_out;

    cudaFuncSetAttribute(gemm_kernel, cudaFuncAttributeMaxDynamicSharedMemorySize, SMEM_BYTES);

    prep_w_kernel<<<512, 256>>>(W);
    gemm_kernel<<<NUM_CTAS, THREADS, SMEM_BYTES>>>(x, b, out);
}

// round 15
// speedup vs baseline: 1.0942x; 1.0512x over previous
#include <cuda_runtime.h>
#include <cuda_fp16.h>
#include <cstdint>

// ===================== problem constants =====================
// x: 262144 rows x 128; W: (8,128,128); b: (8,128)
// CTA job: 128 rows (M) x 128 cols (N) x K=128, K in 2 chunks of 64.
#define N_DIM      128
#define K_DIM      128
#define THREADS    256
#define NUM_CTAS   2048

// ---- smem layout (32-bit words) ----
// [W fp16 frag image: 8192 words][A fp16 2 bufs: 2 x 128 x 36 words][bias 128]
#define OFF_W       0
#define W_IMG_WORDS 8192
#define AROW_W      36                        // words per A row (72 halves) -> LDSM conflict-free
#define ABUF_W      (128 * AROW_W)            // 4608 words per parity buffer
#define OFF_A       W_IMG_WORDS               // 8192
#define OFF_BIAS    (OFF_A + 2 * ABUF_W)      // 17408
#define SMEM_FLOATS (OFF_BIAS + 128)
#define SMEM_BYTES  (SMEM_FLOATS * 4)         // 70,144 (x2 CTAs = 140KB <= 228KB)

// ===================== helpers =====================
__device__ __forceinline__ uint32_t smem_u32(const void* p) {
    uint32_t a;
    asm("{ .reg .u64 t; cvta.to.shared.u64 t, %1; cvt.u32.u64 %0, t; }" : "=r"(a) : "l"(p));
    return a;
}
__device__ __forceinline__ void cp_async16(uint32_t dst, const void* src) {
    asm volatile("cp.async.cg.shared.global [%0], [%1], 16;" :: "r"(dst), "l"(src));
}
#define CP_COMMIT()  asm volatile("cp.async.commit_group;" ::: "memory")
#define CP_WAIT(n)   asm volatile("cp.async.wait_group %0;" :: "n"(n) : "memory")

__device__ __forceinline__ void ldsm_x4(uint32_t& r0, uint32_t& r1, uint32_t& r2, uint32_t& r3,
                                        uint32_t addr) {
    asm volatile("ldmatrix.sync.aligned.m8n8.x4.shared.b16 {%0,%1,%2,%3}, [%4];"
                 : "=r"(r0), "=r"(r1), "=r"(r2), "=r"(r3) : "r"(addr));
}
// m16n8k16 fp16 MMA, fp32 accumulate
__device__ __forceinline__ void mma_f16(float* c, const uint32_t* a, uint32_t b0, uint32_t b1) {
    asm volatile(
        "mma.sync.aligned.m16n8k16.row.col.f32.f16.f16.f32 "
        "{%0,%1,%2,%3}, {%4,%5,%6,%7}, {%8,%9}, {%0,%1,%2,%3};"
        : "+f"(c[0]), "+f"(c[1]), "+f"(c[2]), "+f"(c[3])
        : "r"(a[0]), "r"(a[1]), "r"(a[2]), "r"(a[3]), "r"(b0), "r"(b1));
}

// ===================== W fp16 fragment image (layout validated rounds 8-14) ====
// Per (ch, kc32): 4096 halves (512 float4s). fi4 = (p*2+ks)*32+lane holds
// { b0(nt=2p), b1(nt=2p), b0(nt=2p+1), b1(nt=2p+1) } fp16x2 fragments.
__device__ __align__(16) __half g_Wimg[8 * 4 * 4096];

// Vectorized prep: 1 float4 read + 2 uint32 writes per thread (4 k-elems, same n).
__global__ void prep_w_kernel(const float* __restrict__ W) {
    int t = blockIdx.x * blockDim.x + threadIdx.x;   // 0 .. 32767
    if (t >= 8 * 128 * 32) return;
    int ch  = t >> 12;
    int rem = t & 4095;
    int n   = rem >> 5;
    int k   = (rem & 31) * 4;
    float4 w = *(const float4*)(W + ((size_t)(ch * 128 + n)) * 128 + k);
    __half2 lo = __float22half2_rn(make_float2(w.x, w.y));   // k, k+1
    __half2 hi = __float22half2_rn(make_float2(w.z, w.w));   // k+2, k+3
    int kc = k >> 5;
    int ks = (k >> 4) & 1;
    int bix = (k >> 3) & 1;
    int lane0 = ((n & 7) << 2) | ((k >> 1) & 3);
    int p = n >> 4;
    int ntodd = (n >> 3) & 1;
    int e = ntodd * 2 + bix;
    int fi4 = (p * 2 + ks) * 32 + lane0;
    uint32_t* base = (uint32_t*)(g_Wimg + ((size_t)(ch * 4 + kc)) * 4096);
    base[fi4 * 4 + e]       = *(uint32_t*)&lo;
    base[(fi4 + 1) * 4 + e] = *(uint32_t*)&hi;    // k+2,k+3 -> lane0+1, same e
}

// ===================== main GEMM =====================
__global__ __launch_bounds__(THREADS, 2)
void gemm_kernel(const float* __restrict__ x, const float* __restrict__ bias,
                 float* __restrict__ out) {
    extern __shared__ __align__(16) float smem[];
    const uint32_t sm_base = smem_u32(smem);

    const int tid  = threadIdx.x;
    const int lane = tid & 31;
    const int wid  = tid >> 5;
    const int blk  = blockIdx.x;
    const int ch   = (blk >> 1) & 7;

    const float* a_base = x + (size_t)blk * (128 * K_DIM);
    float*       o_base = out + (size_t)blk * (128 * N_DIM);

    // ---- prologue: W image via cp.async; bias; A chunk 0 (two half-loads) ----
    {
        const __half* wsrc = g_Wimg + ch * 16384;
        uint32_t sw = sm_base + OFF_W * 4u;
#pragma unroll
        for (int j = 0; j < 8; j++) {
            int pid = j * THREADS + tid;
            cp_async16(sw + (uint32_t)pid * 16u, wsrc + pid * 8);
        }
        CP_COMMIT();
    }
    if (tid < 128) smem[OFF_BIAS + tid] = bias[ch * 128 + tid];

    uint32_t* const abufw = (uint32_t*)(smem + OFF_A);

    // per-thread A piece coords: rows arow+{0,32,64,96}, 4-col group apc within a 32-col half
    const int arow = tid >> 3;
    const int apc  = tid & 7;

    float4 v[4];
    // chunk 0, half 0 (cols 0..31)
#pragma unroll
    for (int i = 0; i < 4; i++)
        v[i] = *(const float4*)(a_base + (size_t)(arow + i * 32) * K_DIM + apc * 4);
#pragma unroll
    for (int i = 0; i < 4; i++) {
        __half2 h0 = __float22half2_rn(make_float2(v[i].x, v[i].y));
        __half2 h1 = __float22half2_rn(make_float2(v[i].z, v[i].w));
        uint2 pk; pk.x = *(uint32_t*)&h0; pk.y = *(uint32_t*)&h1;
        *(uint2*)(abufw + (arow + i * 32) * AROW_W + apc * 2) = pk;
    }
    // chunk 0, half 1 (cols 32..63)
#pragma unroll
    for (int i = 0; i < 4; i++)
        v[i] = *(const float4*)(a_base + (size_t)(arow + i * 32) * K_DIM + 32 + apc * 4);
#pragma unroll
    for (int i = 0; i < 4; i++) {
        __half2 h0 = __float22half2_rn(make_float2(v[i].x, v[i].y));
        __half2 h1 = __float22half2_rn(make_float2(v[i].z, v[i].w));
        uint2 pk; pk.x = *(uint32_t*)&h0; pk.y = *(uint32_t*)&h1;
        *(uint2*)(abufw + (arow + i * 32) * AROW_W + 16 + apc * 2) = pk;
    }

    CP_WAIT(0);
    __syncthreads();                 // W image + bias + A buf0 visible

    // 8 warps: 4 over M (32 rows each), 2 over N (64 cols each)
    const int warpM = (wid >> 1) * 32;
    const int h     = (wid & 1);

    float acc[2][8][4];
#pragma unroll
    for (int mt = 0; mt < 2; mt++)
#pragma unroll
        for (int nt = 0; nt < 8; nt++)
#pragma unroll
            for (int q = 0; q < 4; q++) acc[mt][nt][q] = 0.0f;

    // LDSM per-lane byte offset: row = warpM + (lane&7) + ((lane>>3)&1)*8, +8 halves lanes 16-31
    const uint32_t a_lane_b =
        (uint32_t)(((warpM + (lane & 7) + ((lane >> 3) & 1) * 8) * 72 + (lane >> 4) * 8) * 2);
    const uint32_t f16_base = sm_base + OFF_A * 4u;

#pragma unroll
    for (int kc = 0; kc < 2; kc++) {
        const int par = kc;
        const bool havenext = (kc == 0);

        // LDG next chunk half0 (cols 64..95) — covered by the MMA stream below
        if (havenext) {
#pragma unroll
            for (int i = 0; i < 4; i++)
                v[i] = *(const float4*)(a_base + (size_t)(arow + i * 32) * K_DIM
                                        + 64 + apc * 4);
        }

        const uint32_t aL = f16_base + (uint32_t)(par * ABUF_W) * 4u + a_lane_b;
        uint32_t afr[2][2][4];       // ping-pong over ks parity
#pragma unroll
        for (int mt = 0; mt < 2; mt++)
            ldsm_x4(afr[0][mt][0], afr[0][mt][1], afr[0][mt][2], afr[0][mt][3],
                    aL + (uint32_t)(mt * 2304));          // mt*16 rows * 144B

#pragma unroll
        for (int ks = 0; ks < 4; ks++) {                  // 4 k16-steps per 64-chunk
            const int cur = ks & 1, nxt = cur ^ 1;
            const int kc32 = kc * 2 + (ks >> 1);
            const int ks16 = ks & 1;
            const float4* bW = (const float4*)(smem + OFF_W) + kc32 * 512 + h * 256 + lane;

            float4 f0 = bW[0 * 64 + ks16 * 32];
            float4 f1 = bW[1 * 64 + ks16 * 32];
            float4 f2 = bW[2 * 64 + ks16 * 32];
            float4 f3 = bW[3 * 64 + ks16 * 32];

            if (ks < 3) {
#pragma unroll
                for (int mt = 0; mt < 2; mt++)
                    ldsm_x4(afr[nxt][mt][0], afr[nxt][mt][1], afr[nxt][mt][2], afr[nxt][mt][3],
                            aL + (uint32_t)(mt * 2304 + (ks + 1) * 32));
            }

            const float4 fr[4] = {f0, f1, f2, f3};
#pragma unroll
            for (int p = 0; p < 4; p++) {
                uint32_t b0e = __float_as_uint(fr[p].x), b1e = __float_as_uint(fr[p].y);
                uint32_t b0o = __float_as_uint(fr[p].z), b1o = __float_as_uint(fr[p].w);
                mma_f16(acc[0][2 * p],     afr[cur][0], b0e, b1e);
                mma_f16(acc[0][2 * p + 1], afr[cur][0], b0o, b1o);
                mma_f16(acc[1][2 * p],     afr[cur][1], b0e, b1e);
                mma_f16(acc[1][2 * p + 1], afr[cur][1], b0o, b1o);
            }

            // after the ks=1 block: commit half0 of next chunk, start half1 LDG
            if (ks == 1 && havenext) {
#pragma unroll
                for (int i = 0; i < 4; i++) {
                    __half2 h0 = __float22half2_rn(make_float2(v[i].x, v[i].y));
                    __half2 h1 = __float22half2_rn(make_float2(v[i].z, v[i].w));
                    uint2 pk; pk.x = *(uint32_t*)&h0; pk.y = *(uint32_t*)&h1;
                    *(uint2*)(abufw + ABUF_W + (arow + i * 32) * AROW_W + apc * 2) = pk;
                }
#pragma unroll
                for (int i = 0; i < 4; i++)
                    v[i] = *(const float4*)(a_base + (size_t)(arow + i * 32) * K_DIM
                                            + 96 + apc * 4);
            }
        }

        // commit half1 of next chunk; the single loop barrier
        if (havenext) {
#pragma unroll
            for (int i = 0; i < 4; i++) {
                __half2 h0 = __float22half2_rn(make_float2(v[i].x, v[i].y));
                __half2 h1 = __float22half2_rn(make_float2(v[i].z, v[i].w));
                uint2 pk; pk.x = *(uint32_t*)&h0; pk.y = *(uint32_t*)&h1;
                *(uint2*)(abufw + ABUF_W + (arow + i * 32) * AROW_W + 16 + apc * 2) = pk;
            }
            __syncthreads();
        }
    }

    // ---- epilogue: accum + bias -> gmem (float2, full 32B sectors) ----
    const float* sB = smem + OFF_BIAS;
    const int r0 = warpM + (lane >> 2);
    const int n0 = h * 64 + (lane & 3) * 2;
#pragma unroll
    for (int mt = 0; mt < 2; mt++) {
#pragma unroll
        for (int hh = 0; hh < 2; hh++) {
            int row = r0 + mt * 16 + hh * 8;
            float* orow = o_base + (size_t)row * N_DIM;
#pragma unroll
            for (int nt = 0; nt < 8; nt++) {
                int n = n0 + nt * 8;
                float2 vv;
                vv.x = acc[mt][nt][hh * 2 + 0] + sB[n];
                vv.y = acc[mt][nt][hh * 2 + 1] + sB[n + 1];
                *(float2*)(orow + n) = vv;
            }
        }
    }
}

// ===================== launch =====================
extern "C" void kernel_launch(void* const* d_in, const int* in_sizes, int n_in,
                              void* d_out, int out_size) {
    const float* x = (const float*)d_in[0];
    const float* W = (const float*)d_in[1];
    const float* b = (const float*)d_in[2];
    float* out = (float*)d_out;

    cudaFuncSetAttribute(gemm_kernel, cudaFuncAttributeMaxDynamicSharedMemorySize, SMEM_BYTES);

    prep_w_kernel<<<128, 256>>>(W);
    gemm_kernel<<<NUM_CTAS, THREADS, SMEM_BYTES>>>(x, b, out);
}

// round 16
// speedup vs baseline: 1.1076x; 1.0123x over previous
#include <cuda_runtime.h>
#include <cuda_fp16.h>
#include <cstdint>

// ===================== problem constants =====================
// x: 262144 rows x 128; W: (8,128,128); b: (8,128)
// CTA job: 128 rows (M) x 128 cols (N) x K=128. Channel constant per 2 jobs.
#define N_DIM      128
#define K_DIM      128
#define THREADS    256
#define NUM_CTAS   2048
#define K_CHUNK    32
#define NCHUNK     4

// ---- smem layout (32-bit words) ----
// [W fp16 frag image: 8192 words][A fp16 2 bufs: 2x2560 words][bias 128]
#define OFF_W       0
#define W_IMG_WORDS 8192
#define F16_STRIDE_H 40                       // halves per A row -> LDSM conflict-free
#define F16_BUF_WORDS (128 * 20)              // 2560 words = 10KB per parity buf
#define OFF_A       W_IMG_WORDS               // 8192
#define OFF_BIAS    (OFF_A + 2 * F16_BUF_WORDS)   // 13312
#define SMEM_FLOATS (OFF_BIAS + 128)
#define SMEM_BYTES  (SMEM_FLOATS * 4)         // 53,760 (x2 CTAs = 107.5KB)

// ===================== helpers =====================
__device__ __forceinline__ uint32_t smem_u32(const void* p) {
    uint32_t a;
    asm("{ .reg .u64 t; cvta.to.shared.u64 t, %1; cvt.u32.u64 %0, t; }" : "=r"(a) : "l"(p));
    return a;
}
__device__ __forceinline__ void cp_async16(uint32_t dst, const void* src) {
    asm volatile("cp.async.cg.shared.global [%0], [%1], 16;" :: "r"(dst), "l"(src));
}
#define CP_COMMIT()  asm volatile("cp.async.commit_group;" ::: "memory")
#define CP_WAIT(n)   asm volatile("cp.async.wait_group %0;" :: "n"(n) : "memory")

__device__ __forceinline__ void ldsm_x4(uint32_t& r0, uint32_t& r1, uint32_t& r2, uint32_t& r3,
                                        uint32_t addr) {
    asm volatile("ldmatrix.sync.aligned.m8n8.x4.shared.b16 {%0,%1,%2,%3}, [%4];"
                 : "=r"(r0), "=r"(r1), "=r"(r2), "=r"(r3) : "r"(addr));
}
// m16n8k16 fp16 MMA, fp32 accumulate
__device__ __forceinline__ void mma_f16(float* c, const uint32_t* a, uint32_t b0, uint32_t b1) {
    asm volatile(
        "mma.sync.aligned.m16n8k16.row.col.f32.f16.f16.f32 "
        "{%0,%1,%2,%3}, {%4,%5,%6,%7}, {%8,%9}, {%0,%1,%2,%3};"
        : "+f"(c[0]), "+f"(c[1]), "+f"(c[2]), "+f"(c[3])
        : "r"(a[0]), "r"(a[1]), "r"(a[2]), "r"(a[3]), "r"(b0), "r"(b1));
}

// ===================== W fp16 fragment image (layout validated rounds 8-15) ====
// Per (ch, kc): 4096 halves (512 float4s). fi4 = (p*2+ks)*32+lane holds
// { b0(nt=2p), b1(nt=2p), b0(nt=2p+1), b1(nt=2p+1) } fp16x2 fragments.
__device__ __align__(16) __half g_Wimg[8 * 4 * 4096];

// Vectorized prep (validated round 15): 1 float4 read + 2 uint32 writes per thread.
__global__ void prep_w_kernel(const float* __restrict__ W) {
    int t = blockIdx.x * blockDim.x + threadIdx.x;   // 0 .. 32767
    if (t < 8 * 128 * 32) {
        int ch  = t >> 12;
        int rem = t & 4095;
        int n   = rem >> 5;
        int k   = (rem & 31) * 4;
        float4 w = *(const float4*)(W + ((size_t)(ch * 128 + n)) * 128 + k);
        __half2 lo = __float22half2_rn(make_float2(w.x, w.y));   // k, k+1
        __half2 hi = __float22half2_rn(make_float2(w.z, w.w));   // k+2, k+3
        int kc = k >> 5;
        int ks = (k >> 4) & 1;
        int bix = (k >> 3) & 1;
        int lane0 = ((n & 7) << 2) | ((k >> 1) & 3);
        int p = n >> 4;
        int ntodd = (n >> 3) & 1;
        int e = ntodd * 2 + bix;
        int fi4 = (p * 2 + ks) * 32 + lane0;
        uint32_t* base = (uint32_t*)(g_Wimg + ((size_t)(ch * 4 + kc)) * 4096);
        base[fi4 * 4 + e]       = *(uint32_t*)&lo;
        base[(fi4 + 1) * 4 + e] = *(uint32_t*)&hi;    // k+2,k+3 -> lane0+1, same e
    }
    // PDL: writes above are visible to dependents after their griddepcontrol.wait
    asm volatile("griddepcontrol.launch_dependents;" ::: "memory");
}

// ===================== main GEMM (exact round-9 loop; PDL prologue) =====================
__global__ __launch_bounds__(THREADS, 2)
void gemm_kernel(const float* __restrict__ x, const float* __restrict__ bias,
                 float* __restrict__ out) {
    extern __shared__ __align__(16) float smem[];
    const uint32_t sm_base = smem_u32(smem);

    const int tid  = threadIdx.x;
    const int lane = tid & 31;
    const int wid  = tid >> 5;
    const int blk  = blockIdx.x;
    const int ch   = (blk >> 1) & 7;

    const float* a_base = x + (size_t)blk * (128 * K_DIM);
    float*       o_base = out + (size_t)blk * (128 * N_DIM);

    // per-thread A piece coordinates: pid = i*256+tid -> row pid>>3, 4-col group pid&7
    const int arow = tid >> 3;          // rows handled: arow, arow+32, arow+64, arow+96
    const int apc  = tid & 7;

    // ---- PDL-independent work first: A chunk-0 LDGs + bias (not written by prep) ----
    float4 v[4];
#pragma unroll
    for (int i = 0; i < 4; i++)
        v[i] = *(const float4*)(a_base + (size_t)(arow + i * 32) * K_DIM + apc * 4);
    float bval = (tid < 128) ? bias[ch * 128 + tid] : 0.0f;

    // ---- wait for prep's W image, then pull it via cp.async ----
    asm volatile("griddepcontrol.wait;" ::: "memory");
    {
        const __half* wsrc = g_Wimg + ch * 16384;
        uint32_t sw = sm_base + OFF_W * 4u;
#pragma unroll
        for (int j = 0; j < 8; j++) {
            int pid = j * THREADS + tid;
            cp_async16(sw + (uint32_t)pid * 16u, wsrc + pid * 8);
        }
        CP_COMMIT();
    }
    if (tid < 128) smem[OFF_BIAS + tid] = bval;

    // 8 warps: 4 over M (32 rows each), 2 over N (64 cols each)
    const int warpM = (wid >> 1) * 32;
    const int h     = (wid & 1);

    float acc[2][8][4];
#pragma unroll
    for (int mt = 0; mt < 2; mt++)
#pragma unroll
        for (int nt = 0; nt < 8; nt++)
#pragma unroll
            for (int q = 0; q < 4; q++) acc[mt][nt][q] = 0.0f;

    uint32_t* const abufw = (uint32_t*)(smem + OFF_A);   // word view of fp16 bufs

    // STS chunk 0 -> buf 0
#pragma unroll
    for (int i = 0; i < 4; i++) {
        __half2 h0 = __float22half2_rn(make_float2(v[i].x, v[i].y));
        __half2 h1 = __float22half2_rn(make_float2(v[i].z, v[i].w));
        uint2 pk; pk.x = *(uint32_t*)&h0; pk.y = *(uint32_t*)&h1;
        *(uint2*)(abufw + (arow + i * 32) * 20 + apc * 2) = pk;
    }

    CP_WAIT(0);
    __syncthreads();                     // W image + bias + A buf0 visible

    // LDSM per-lane base (halves): row = warpM + (lane&7) + ((lane>>3)&1)*8, +8 halves lanes 16-31
    const uint32_t a_lane_h =
        (uint32_t)((warpM + (lane & 7) + ((lane >> 3) & 1) * 8) * F16_STRIDE_H
                   + (lane >> 4) * 8);
    const uint32_t f16_base = sm_base + OFF_A * 4u;

#pragma unroll
    for (int kc = 0; kc < NCHUNK; kc++) {
        const int par = kc & 1;

        // LDG next chunk (covered by the MMA block below)
        if (kc < NCHUNK - 1) {
#pragma unroll
            for (int i = 0; i < 4; i++)
                v[i] = *(const float4*)(a_base + (size_t)(arow + i * 32) * K_DIM
                                        + (kc + 1) * K_CHUNK + apc * 4);
        }

        // ---- MMA phase on buf[par], W frags for this kc ----
        const float4* bW = (const float4*)(smem + OFF_W) + kc * 512 + h * 256 + lane;
        const uint32_t aL = f16_base + (uint32_t)(par * F16_BUF_WORDS) * 4u + a_lane_h * 2u;

        uint32_t afr[2][2][4];
#pragma unroll
        for (int mt = 0; mt < 2; mt++)
            ldsm_x4(afr[0][mt][0], afr[0][mt][1], afr[0][mt][2], afr[0][mt][3],
                    aL + (uint32_t)(mt * 16 * F16_STRIDE_H * 2));

#pragma unroll
        for (int ks = 0; ks < 2; ks++) {
            float4 f0 = bW[0 * 64 + ks * 32];
            float4 f1 = bW[1 * 64 + ks * 32];
            float4 f2 = bW[2 * 64 + ks * 32];
            float4 f3 = bW[3 * 64 + ks * 32];

            if (ks == 0) {
#pragma unroll
                for (int mt = 0; mt < 2; mt++)
                    ldsm_x4(afr[1][mt][0], afr[1][mt][1], afr[1][mt][2], afr[1][mt][3],
                            aL + (uint32_t)((mt * 16 * F16_STRIDE_H + 16) * 2));
            }

            const float4 fr[4] = {f0, f1, f2, f3};
#pragma unroll
            for (int p = 0; p < 4; p++) {
                uint32_t b0e = __float_as_uint(fr[p].x), b1e = __float_as_uint(fr[p].y);
                uint32_t b0o = __float_as_uint(fr[p].z), b1o = __float_as_uint(fr[p].w);
                mma_f16(acc[0][2 * p],     afr[ks][0], b0e, b1e);
                mma_f16(acc[0][2 * p + 1], afr[ks][0], b0o, b1o);
                mma_f16(acc[1][2 * p],     afr[ks][1], b0e, b1e);
                mma_f16(acc[1][2 * p + 1], afr[ks][1], b0o, b1o);
            }
        }

        // ---- cvt + STS next chunk into opposite buffer; single barrier ----
        if (kc < NCHUNK - 1) {
            const int npar = par ^ 1;
#pragma unroll
            for (int i = 0; i < 4; i++) {
                __half2 h0 = __float22half2_rn(make_float2(v[i].x, v[i].y));
                __half2 h1 = __float22half2_rn(make_float2(v[i].z, v[i].w));
                uint2 pk; pk.x = *(uint32_t*)&h0; pk.y = *(uint32_t*)&h1;
                *(uint2*)(abufw + npar * F16_BUF_WORDS + (arow + i * 32) * 20 + apc * 2) = pk;
            }
            __syncthreads();
        }
    }

    // ---- epilogue: accum + bias -> gmem (float2, full 32B sectors) ----
    const float* sB = smem + OFF_BIAS;
    const int r0 = warpM + (lane >> 2);
    const int n0 = h * 64 + (lane & 3) * 2;
#pragma unroll
    for (int mt = 0; mt < 2; mt++) {
#pragma unroll
        for (int hh = 0; hh < 2; hh++) {
            int row = r0 + mt * 16 + hh * 8;
            float* orow = o_base + (size_t)row * N_DIM;
#pragma unroll
            for (int nt = 0; nt < 8; nt++) {
                int n = n0 + nt * 8;
                float2 vv;
                vv.x = acc[mt][nt][hh * 2 + 0] + sB[n];
                vv.y = acc[mt][nt][hh * 2 + 1] + sB[n + 1];
                *(float2*)(orow + n) = vv;
            }
        }
    }
}

// ===================== launch (PDL between prep and gemm) =====================
extern "C" void kernel_launch(void* const* d_in, const int* in_sizes, int n_in,
                              void* d_out, int out_size) {
    const float* x = (const float*)d_in[0];
    const float* W = (const float*)d_in[1];
    const float* b = (const float*)d_in[2];
    float* out = (float*)d_out;

    cudaFuncSetAttribute(gemm_kernel, cudaFuncAttributeMaxDynamicSharedMemorySize, SMEM_BYTES);

    prep_w_kernel<<<128, 256>>>(W);

    // gemm with programmatic dependent launch: launch setup overlaps prep execution;
    // in-kernel griddepcontrol.wait provides the memory dependency on g_Wimg.
    cudaLaunchConfig_t cfg = {};
    cfg.gridDim = dim3(NUM_CTAS, 1, 1);
    cfg.blockDim = dim3(THREADS, 1, 1);
    cfg.dynamicSmemBytes = SMEM_BYTES;
    cfg.stream = 0;
    cudaLaunchAttribute attr[1];
    attr[0].id = cudaLaunchAttributeProgrammaticStreamSerialization;
    attr[0].val.programmaticStreamSerializationAllowed = 1;
    cfg.attrs = attr;
    cfg.numAttrs = 1;
    cudaError_t err = cudaLaunchKernelEx(&cfg, gemm_kernel, x, b, out);
    if (err != cudaSuccess) {
        (void)cudaGetLastError();   // clear; fall back to a plain serialized launch
        gemm_kernel<<<NUM_CTAS, THREADS, SMEM_BYTES>>>(x, b, out);
    }
}